// round 11
// baseline (speedup 1.0000x reference)
#include <cuda_runtime.h>
#include <cuda_fp16.h>
#include <cstdint>

#define NN 262144
#define MD 512
#define MSG 1024
#define NU 65536
#define NKC 24
#define TILEB 16384
#define STAGEB 40960
#define NSTG 3
#define BUF_IN_OFF (NSTG*STAGEB)
#define MBAR_OFF  (BUF_IN_OFF + 33792)
#define SMEMSZ    (MBAR_OFF + 64)
#define BUF_R_OFF  0
#define BUF_Z_OFF  34816
#define BUF_H_OFF  69632
#define EPIPITCH 132

__device__ __align__(1024) __half g_A[(size_t)NU * 1536];
__device__ __align__(1024) __half g_B[(size_t)3 * 512 * 1536];
__device__ int g_nid64;
__device__ unsigned g_bitmap[NN / 32];   // updated-row bitmap (rebuilt every call)

static __device__ __forceinline__ long long fetch_nid(const void* nid, int i) {
    if (g_nid64) return ((const long long*)nid)[i];
    return (long long)((const int*)nid)[i];
}

static __device__ __forceinline__ uint32_t s2u(const void* p) {
    uint32_t r;
    asm("{ .reg .u64 t; cvta.to.shared.u64 t, %1; cvt.u32.u64 %0, t; }" : "=r"(r) : "l"(p));
    return r;
}

#define MBAR_INIT(a, c) asm volatile("mbarrier.init.shared.b64 [%0], %1;" :: "r"(a), "r"((uint32_t)(c)) : "memory")
#define MBAR_EXPECT(a, b) asm volatile("mbarrier.arrive.expect_tx.shared.b64 _, [%0], %1;" :: "r"(a), "r"((uint32_t)(b)) : "memory")

#define MBAR_WAIT(mb, ph) do { \
    uint32_t _m = (uint32_t)(mb), _p = (uint32_t)(ph), _d; \
    asm volatile("{\n\t.reg .pred p;\n\t" \
        "mbarrier.try_wait.parity.acquire.cta.shared::cta.b64 p, [%1], %2;\n\t" \
        "selp.b32 %0, 1, 0, p;\n\t}" : "=r"(_d) : "r"(_m), "r"(_p) : "memory"); \
    if (!_d) { \
        asm volatile("{\n\t.reg .pred P1;\n\t" \
            "WL_%=:\n\t" \
            "mbarrier.try_wait.parity.acquire.cta.shared::cta.b64 P1, [%0], %1, 0x989680;\n\t" \
            "@P1 bra.uni WD_%=;\n\t" \
            "bra.uni WL_%=;\n\t" \
            "WD_%=:\n\t}" :: "r"(_m), "r"(_p) : "memory"); \
    } \
} while (0)

#define FENCE_ASYNC() asm volatile("fence.proxy.async.shared::cta;" ::: "memory")

static __device__ __forceinline__ void bulk_g2s(uint32_t dst, const void* src, uint32_t bytes, uint32_t mb) {
    asm volatile("cp.async.bulk.shared::cluster.global.mbarrier::complete_tx::bytes [%0], [%1], %2, [%3];"
        :: "r"(dst), "l"((unsigned long long)__cvta_generic_to_global((void*)src)), "r"(bytes), "r"(mb)
        : "memory");
}

static __device__ __forceinline__ uint32_t sw128(uint32_t bo) {
    return bo ^ ((bo >> 3) & 0x70);
}

static __device__ __forceinline__ void ldsm4(uint32_t& r0, uint32_t& r1, uint32_t& r2, uint32_t& r3, uint32_t a) {
    asm volatile("ldmatrix.sync.aligned.m8n8.x4.shared.b16 {%0,%1,%2,%3}, [%4];"
        : "=r"(r0), "=r"(r1), "=r"(r2), "=r"(r3) : "r"(a));
}

static __device__ __forceinline__ void mma16816(float* d, uint32_t a0, uint32_t a1, uint32_t a2, uint32_t a3,
                                                uint32_t b0, uint32_t b1) {
    asm volatile("mma.sync.aligned.m16n8k16.row.col.f32.f16.f16.f32 "
        "{%0,%1,%2,%3}, {%4,%5,%6,%7}, {%8,%9}, {%0,%1,%2,%3};"
        : "+f"(d[0]), "+f"(d[1]), "+f"(d[2]), "+f"(d[3])
        : "r"(a0), "r"(a1), "r"(a2), "r"(a3), "r"(b0), "r"(b1));
}

// -------- detect node_ids dtype --------
__global__ void detect_nid(const int* __restrict__ nid_words) {
    int lane = threadIdx.x;
    int odd_nonzero = (lane & 1) && (nid_words[lane] != 0);
    unsigned m = __ballot_sync(0xFFFFFFFFu, odd_nonzero);
    __shared__ int cnt;
    if (threadIdx.x == 0) cnt = 0;
    __syncthreads();
    if ((threadIdx.x & 31) == 0) atomicAdd(&cnt, __popc(m));
    __syncthreads();
    if (threadIdx.x == 0) g_nid64 = (cnt == 0) ? 1 : 0;
}

// -------- bitmap clear + set --------
__global__ void __launch_bounds__(256) bm_clear() {
    int i = blockIdx.x * 256 + threadIdx.x;
    if (i < NN / 32) g_bitmap[i] = 0u;
}
__global__ void __launch_bounds__(256) bm_set(const void* __restrict__ nid) {
    int i = blockIdx.x * 256 + threadIdx.x;
    if (i < NU) {
        long long n = fetch_nid(nid, i);
        atomicOr(&g_bitmap[n >> 5], 1u << (n & 31));
    }
}

// -------- copy of NON-updated memory rows (overlaps with GEMM) --------
__global__ void __launch_bounds__(256) copy_skip(const float4* __restrict__ mem, float4* __restrict__ out) {
    size_t i = (size_t)blockIdx.x * 256 + threadIdx.x;   // float4 index, 128 per row
    const size_t nm = (size_t)NN * (MD / 4);
    if (i < nm) {
        unsigned row = (unsigned)(i >> 7);
        if (!(g_bitmap[row >> 5] & (1u << (row & 31)))) out[i] = mem[i];
    }
}

// -------- last_update copy (main stream, before prep_a's scatter) --------
__global__ void __launch_bounds__(256) copy_lu(const float4* __restrict__ lu, float4* __restrict__ out_lu) {
    size_t i = (size_t)blockIdx.x * 256 + threadIdx.x;
    if (i < NN / 4) out_lu[i] = lu[i];
}

// -------- W -> g_B fp16 swizzled tiles --------
__global__ void __launch_bounds__(192) prep_b(const float* __restrict__ Wih, const float* __restrict__ Whh) {
    int j = blockIdx.x, c = threadIdx.x;
    const float* s = (c < 128) ? (Wih + (size_t)j * MSG + c * 8) : (Whh + (size_t)j * MD + (c - 128) * 8);
    float4 a = ((const float4*)s)[0], b = ((const float4*)s)[1];
    uint4 u; __half* hp = (__half*)&u;
    hp[0] = __float2half_rn(a.x); hp[1] = __float2half_rn(a.y);
    hp[2] = __float2half_rn(a.z); hp[3] = __float2half_rn(a.w);
    hp[4] = __float2half_rn(b.x); hp[5] = __float2half_rn(b.y);
    hp[6] = __float2half_rn(b.z); hp[7] = __float2half_rn(b.w);
    int g = j >> 9, jl = j & 511;
    size_t t = ((size_t)(g * 4 + (jl >> 7)) * NKC + (c >> 3)) * TILEB;
    uint32_t bo = (uint32_t)((jl & 127) * 128 + (c & 7) * 16);
    *(uint4*)((char*)g_B + t + sw128(bo)) = u;
}

// -------- gather+convert A -> g_A; scatter last_update --------
__global__ void __launch_bounds__(192) prep_a(const float* __restrict__ msg, const float* __restrict__ mem,
                                              const void* __restrict__ nid, const float* __restrict__ ts,
                                              float* __restrict__ out_lu) {
    int i = blockIdx.x, c = threadIdx.x;
    long long n = fetch_nid(nid, i);
    if (c == 0) out_lu[n] = ts[i];
    const float* s = (c < 128) ? (msg + (size_t)i * MSG + c * 8) : (mem + (size_t)n * MD + (c - 128) * 8);
    float4 a = ((const float4*)s)[0], b = ((const float4*)s)[1];
    uint4 u; __half* hp = (__half*)&u;
    hp[0] = __float2half_rn(a.x); hp[1] = __float2half_rn(a.y);
    hp[2] = __float2half_rn(a.z); hp[3] = __float2half_rn(a.w);
    hp[4] = __float2half_rn(b.x); hp[5] = __float2half_rn(b.y);
    hp[6] = __float2half_rn(b.z); hp[7] = __float2half_rn(b.w);
    size_t t = ((size_t)(i >> 7) * NKC + (c >> 3)) * TILEB;
    uint32_t bo = (uint32_t)((i & 127) * 128 + (c & 7) * 16);
    *(uint4*)((char*)g_A + t + sw128(bo)) = u;
}

// -------- fused GEMM (mma.sync) + GRU + scatter --------
// grid 4096 = 512 m-tiles x 8 n64-chunks. 768 threads = 24 warps.
// warp w: gate g = w>>3 (0=r,1=z,2=n), mb = (w>>1)&3 (32 M-rows), nh2 = w&1 (n32 half).
__global__ void __launch_bounds__(768) gru_gemm(const float* __restrict__ mem, const void* __restrict__ nid,
                                                const float* __restrict__ bih, const float* __restrict__ bhh,
                                                float* __restrict__ out) {
    extern __shared__ char smem[];
    const uint32_t sb = s2u(smem);
    const int tid = threadIdx.x, w = tid >> 5, lane = tid & 31;
    const int g = w >> 3, mb = (w >> 1) & 3, nh2 = w & 1;
    const int mt = blockIdx.x >> 3, nc = blockIdx.x & 7;
    const int nc128 = nc >> 1, nh = nc & 1;
    const uint32_t mbar = sb + MBAR_OFF;

    if (tid == 0) {
        MBAR_INIT(mbar, 1); MBAR_INIT(mbar + 8, 1); MBAR_INIT(mbar + 16, 1);
        FENCE_ASYNC();
    }
    __syncthreads();

    const char* Ab = (const char*)g_A + (size_t)mt * NKC * TILEB;

    if (tid == 0) {
        #pragma unroll
        for (int c = 0; c < NSTG; c++) {
            uint32_t st = sb + c * STAGEB, mbr = mbar + c * 8;
            MBAR_EXPECT(mbr, STAGEB);
            bulk_g2s(st, Ab + (size_t)c * TILEB, TILEB, mbr);
            #pragma unroll
            for (int gg = 0; gg < 3; gg++)
                bulk_g2s(st + TILEB + gg * 8192,
                         (const char*)g_B + ((size_t)((gg * 4 + nc128) * NKC + c)) * TILEB + nh * 8192,
                         8192, mbr);
        }
    }

    float acc[2][4][4];
    #pragma unroll
    for (int t = 0; t < 2; t++)
        #pragma unroll
        for (int nt = 0; nt < 4; nt++)
            #pragma unroll
            for (int q = 0; q < 4; q++) acc[t][nt][q] = 0.0f;

    float* bufIn = (float*)(smem + BUF_IN_OFF);

    for (int c = 0; c < NKC; c++) {
        const int s = c % 3;
        MBAR_WAIT(mbar + s * 8, (c / 3) & 1);

        if (c == 16 && g == 2) {
            #pragma unroll
            for (int t = 0; t < 2; t++)
                #pragma unroll
                for (int nt = 0; nt < 4; nt++) {
                    int row0 = mb * 32 + t * 16 + (lane >> 2);
                    int col0 = nh2 * 32 + nt * 8 + 2 * (lane & 3);
                    bufIn[col0 * EPIPITCH + row0]           = acc[t][nt][0];
                    bufIn[(col0 + 1) * EPIPITCH + row0]     = acc[t][nt][1];
                    bufIn[col0 * EPIPITCH + row0 + 8]       = acc[t][nt][2];
                    bufIn[(col0 + 1) * EPIPITCH + row0 + 8] = acc[t][nt][3];
                    acc[t][nt][0] = acc[t][nt][1] = acc[t][nt][2] = acc[t][nt][3] = 0.0f;
                }
        }

        const uint32_t stA = sb + s * STAGEB;
        const uint32_t stB = stA + TILEB + g * 8192;
        #pragma unroll
        for (int ks = 0; ks < 4; ks++) {
            uint32_t a[2][4];
            #pragma unroll
            for (int t = 0; t < 2; t++) {
                int row = mb * 32 + t * 16 + (lane & 7) + ((lane >> 3) & 1) * 8;
                int kb = ks * 32 + ((lane >> 4) & 1) * 16;
                ldsm4(a[t][0], a[t][1], a[t][2], a[t][3], stA + sw128(row * 128 + kb));
            }
            #pragma unroll
            for (int p = 0; p < 2; p++) {
                int rown = nh2 * 32 + p * 16 + (lane & 7) + ((lane >> 4) & 1) * 8;
                int kb = ks * 32 + ((lane >> 3) & 1) * 16;
                uint32_t b0, b1, b2, b3;
                ldsm4(b0, b1, b2, b3, stB + sw128(rown * 128 + kb));
                #pragma unroll
                for (int t = 0; t < 2; t++) {
                    mma16816(acc[t][2 * p],     a[t][0], a[t][1], a[t][2], a[t][3], b0, b1);
                    mma16816(acc[t][2 * p + 1], a[t][0], a[t][1], a[t][2], a[t][3], b2, b3);
                }
            }
        }
        __syncthreads();
        if (tid == 0 && c + 3 < NKC) {
            const int cn = c + 3;
            uint32_t st = sb + s * STAGEB, mbr = mbar + s * 8;
            MBAR_EXPECT(mbr, STAGEB);
            bulk_g2s(st, Ab + (size_t)cn * TILEB, TILEB, mbr);
            #pragma unroll
            for (int gg = 0; gg < 3; gg++)
                bulk_g2s(st + TILEB + gg * 8192,
                         (const char*)g_B + ((size_t)((gg * 4 + nc128) * NKC + cn)) * TILEB + nh * 8192,
                         8192, mbr);
        }
    }

    float* bufG = (float*)(smem + (g == 0 ? BUF_R_OFF : (g == 1 ? BUF_Z_OFF : BUF_H_OFF)));
    #pragma unroll
    for (int t = 0; t < 2; t++)
        #pragma unroll
        for (int nt = 0; nt < 4; nt++) {
            int row0 = mb * 32 + t * 16 + (lane >> 2);
            int col0 = nh2 * 32 + nt * 8 + 2 * (lane & 3);
            bufG[col0 * EPIPITCH + row0]           = acc[t][nt][0];
            bufG[(col0 + 1) * EPIPITCH + row0]     = acc[t][nt][1];
            bufG[col0 * EPIPITCH + row0 + 8]       = acc[t][nt][2];
            bufG[(col0 + 1) * EPIPITCH + row0 + 8] = acc[t][nt][3];
        }
    __syncthreads();

    if (w < 4) {
        const float* BR = (const float*)(smem + BUF_R_OFF);
        const float* BZ = (const float*)(smem + BUF_Z_OFF);
        const float* BH = (const float*)(smem + BUF_H_OFF);
        const float* BI = (const float*)(smem + BUF_IN_OFF);
        int row = w * 32 + lane;
        int gi = mt * 128 + row;
        long long n = fetch_nid(nid, gi);
        const float4* hp = (const float4*)(mem + (size_t)n * MD + nc * 64);
        float4* op = (float4*)(out + (size_t)n * MD + nc * 64);
        const int j0 = nc * 64;
        #pragma unroll 4
        for (int jq = 0; jq < 16; jq++) {
            float4 h4 = hp[jq];
            float o[4];
            const float* hv = (const float*)&h4;
            #pragma unroll
            for (int q = 0; q < 4; q++) {
                int j = jq * 4 + q;
                int jg = j0 + j;
                float cr = BR[j * EPIPITCH + row] + bih[jg] + bhh[jg];
                float cz = BZ[j * EPIPITCH + row] + bih[512 + jg] + bhh[512 + jg];
                float ci = BI[j * EPIPITCH + row] + bih[1024 + jg];
                float ch = BH[j * EPIPITCH + row] + bhh[1024 + jg];
                float r = 1.0f / (1.0f + __expf(-cr));
                float z = 1.0f / (1.0f + __expf(-cz));
                float e = __expf(2.0f * (ci + r * ch));
                float nn = 1.0f - 2.0f / (e + 1.0f);
                o[q] = (1.0f - z) * nn + z * hv[q];
            }
            op[jq] = make_float4(o[0], o[1], o[2], o[3]);
        }
    }
}

extern "C" void kernel_launch(void* const* d_in, const int* in_sizes, int n_in,
                              void* d_out, int out_size) {
    const float* mem = (const float*)d_in[0];
    const float* lu = (const float*)d_in[1];
    const void* nid = d_in[2];
    const float* msg = (const float*)d_in[3];
    const float* ts = (const float*)d_in[4];
    const float* Wih = (const float*)d_in[5];
    const float* Whh = (const float*)d_in[6];
    const float* bih = (const float*)d_in[7];
    const float* bhh = (const float*)d_in[8];
    float* out = (float*)d_out;
    float* out_lu = out + (size_t)NN * MD;

    // side stream + fork/join events (created once; host-side resources only,
    // identical captured work every call)
    static cudaStream_t s2 = nullptr;
    static cudaEvent_t evF = nullptr, evJ = nullptr;
    if (!s2) {
        cudaStreamCreateWithFlags(&s2, cudaStreamNonBlocking);
        cudaEventCreateWithFlags(&evF, cudaEventDisableTiming);
        cudaEventCreateWithFlags(&evJ, cudaEventDisableTiming);
    }

    cudaFuncSetAttribute(gru_gemm, cudaFuncAttributeMaxDynamicSharedMemorySize, SMEMSZ);

    detect_nid<<<1, 128>>>((const int*)nid);
    bm_clear<<<(NN / 32 + 255) / 256, 256>>>();
    bm_set<<<(NU + 255) / 256, 256>>>(nid);

    // fork: bulk copy of non-updated rows overlaps with prep + GEMM
    cudaEventRecord(evF, 0);
    cudaStreamWaitEvent(s2, evF, 0);
    copy_skip<<<(NN * (MD / 4) + 255) / 256, 256, 0, s2>>>((const float4*)mem, (float4*)out);
    cudaEventRecord(evJ, s2);

    copy_lu<<<(NN / 4 + 255) / 256, 256>>>((const float4*)lu, (float4*)out_lu);
    prep_b<<<1536, 192>>>(Wih, Whh);
    prep_a<<<NU, 192>>>(msg, mem, nid, ts, out_lu);
    gru_gemm<<<4096, 768, SMEMSZ>>>(mem, nid, bih, bhh, out);

    // join: output complete only when the skip-copy also finished
    cudaStreamWaitEvent(0, evJ, 0);
}

// round 13
// speedup vs baseline: 1.1355x; 1.1355x over previous
#include <cuda_runtime.h>
#include <cuda_fp16.h>
#include <cstdint>

#define NN 262144
#define MD 512
#define MSG 1024
#define NU 65536
#define NKC 24
#define TILEB 16384
#define STAGEB 40960
#define NSTG 3
#define BUF_IN_OFF (NSTG*STAGEB)
#define MBAR_OFF  (BUF_IN_OFF + 33792)
#define SMEMSZ    (MBAR_OFF + 64)
#define BUF_R_OFF  0
#define BUF_Z_OFF  34816
#define BUF_H_OFF  69632
#define EPIPITCH 132

__device__ __align__(1024) __half g_A[(size_t)NU * 1536];
__device__ __align__(1024) __half g_B[(size_t)3 * 512 * 1536];
__device__ int g_nid64;
__device__ unsigned g_bitmap[NN / 32];

static __device__ __forceinline__ long long fetch_nid(const void* nid, int i) {
    if (g_nid64) return ((const long long*)nid)[i];
    return (long long)((const int*)nid)[i];
}

static __device__ __forceinline__ uint32_t s2u(const void* p) {
    uint32_t r;
    asm("{ .reg .u64 t; cvta.to.shared.u64 t, %1; cvt.u32.u64 %0, t; }" : "=r"(r) : "l"(p));
    return r;
}

#define MBAR_INIT(a, c) asm volatile("mbarrier.init.shared.b64 [%0], %1;" :: "r"(a), "r"((uint32_t)(c)) : "memory")
#define MBAR_EXPECT(a, b) asm volatile("mbarrier.arrive.expect_tx.shared.b64 _, [%0], %1;" :: "r"(a), "r"((uint32_t)(b)) : "memory")

#define MBAR_WAIT(mb, ph) do { \
    uint32_t _m = (uint32_t)(mb), _p = (uint32_t)(ph), _d; \
    asm volatile("{\n\t.reg .pred p;\n\t" \
        "mbarrier.try_wait.parity.acquire.cta.shared::cta.b64 p, [%1], %2;\n\t" \
        "selp.b32 %0, 1, 0, p;\n\t}" : "=r"(_d) : "r"(_m), "r"(_p) : "memory"); \
    if (!_d) { \
        asm volatile("{\n\t.reg .pred P1;\n\t" \
            "WL_%=:\n\t" \
            "mbarrier.try_wait.parity.acquire.cta.shared::cta.b64 P1, [%0], %1, 0x989680;\n\t" \
            "@P1 bra.uni WD_%=;\n\t" \
            "bra.uni WL_%=;\n\t" \
            "WD_%=:\n\t}" :: "r"(_m), "r"(_p) : "memory"); \
    } \
} while (0)

#define FENCE_ASYNC() asm volatile("fence.proxy.async.shared::cta;" ::: "memory")
// barrier for the 12 compute warps only (copy warps never participate)
#define BAR_COMPUTE() asm volatile("bar.sync 1, 384;" ::: "memory")

static __device__ __forceinline__ void bulk_g2s(uint32_t dst, const void* src, uint32_t bytes, uint32_t mb) {
    asm volatile("cp.async.bulk.shared::cluster.global.mbarrier::complete_tx::bytes [%0], [%1], %2, [%3];"
        :: "r"(dst), "l"((unsigned long long)__cvta_generic_to_global((void*)src)), "r"(bytes), "r"(mb)
        : "memory");
}

static __device__ __forceinline__ uint32_t sw128(uint32_t bo) {
    return bo ^ ((bo >> 3) & 0x70);
}

static __device__ __forceinline__ void ldsm4(uint32_t& r0, uint32_t& r1, uint32_t& r2, uint32_t& r3, uint32_t a) {
    asm volatile("ldmatrix.sync.aligned.m8n8.x4.shared.b16 {%0,%1,%2,%3}, [%4];"
        : "=r"(r0), "=r"(r1), "=r"(r2), "=r"(r3) : "r"(a));
}

static __device__ __forceinline__ void mma16816(float* d, uint32_t a0, uint32_t a1, uint32_t a2, uint32_t a3,
                                                uint32_t b0, uint32_t b1) {
    asm volatile("mma.sync.aligned.m16n8k16.row.col.f32.f16.f16.f32 "
        "{%0,%1,%2,%3}, {%4,%5,%6,%7}, {%8,%9}, {%0,%1,%2,%3};"
        : "+f"(d[0]), "+f"(d[1]), "+f"(d[2]), "+f"(d[3])
        : "r"(a0), "r"(a1), "r"(a2), "r"(a3), "r"(b0), "r"(b1));
}

// -------- detect node_ids dtype --------
__global__ void detect_nid(const int* __restrict__ nid_words) {
    int lane = threadIdx.x;
    int odd_nonzero = (lane & 1) && (nid_words[lane] != 0);
    unsigned m = __ballot_sync(0xFFFFFFFFu, odd_nonzero);
    __shared__ int cnt;
    if (threadIdx.x == 0) cnt = 0;
    __syncthreads();
    if ((threadIdx.x & 31) == 0) atomicAdd(&cnt, __popc(m));
    __syncthreads();
    if (threadIdx.x == 0) g_nid64 = (cnt == 0) ? 1 : 0;
}

// -------- bitmap clear + set --------
__global__ void __launch_bounds__(256) bm_clear() {
    int i = blockIdx.x * 256 + threadIdx.x;
    if (i < NN / 32) g_bitmap[i] = 0u;
}
__global__ void __launch_bounds__(256) bm_set(const void* __restrict__ nid) {
    int i = blockIdx.x * 256 + threadIdx.x;
    if (i < NU) {
        long long n = fetch_nid(nid, i);
        atomicOr(&g_bitmap[n >> 5], 1u << (n & 31));
    }
}

// -------- last_update copy --------
__global__ void __launch_bounds__(256) copy_lu(const float4* __restrict__ lu, float4* __restrict__ out_lu) {
    size_t i = (size_t)blockIdx.x * 256 + threadIdx.x;
    if (i < NN / 4) out_lu[i] = lu[i];
}

// -------- W -> g_B fp16 swizzled tiles --------
__global__ void __launch_bounds__(192) prep_b(const float* __restrict__ Wih, const float* __restrict__ Whh) {
    int j = blockIdx.x, c = threadIdx.x;
    const float* s = (c < 128) ? (Wih + (size_t)j * MSG + c * 8) : (Whh + (size_t)j * MD + (c - 128) * 8);
    float4 a = ((const float4*)s)[0], b = ((const float4*)s)[1];
    uint4 u; __half* hp = (__half*)&u;
    hp[0] = __float2half_rn(a.x); hp[1] = __float2half_rn(a.y);
    hp[2] = __float2half_rn(a.z); hp[3] = __float2half_rn(a.w);
    hp[4] = __float2half_rn(b.x); hp[5] = __float2half_rn(b.y);
    hp[6] = __float2half_rn(b.z); hp[7] = __float2half_rn(b.w);
    int g = j >> 9, jl = j & 511;
    size_t t = ((size_t)(g * 4 + (jl >> 7)) * NKC + (c >> 3)) * TILEB;
    uint32_t bo = (uint32_t)((jl & 127) * 128 + (c & 7) * 16);
    *(uint4*)((char*)g_B + t + sw128(bo)) = u;
}

// -------- gather+convert A -> g_A; scatter last_update --------
__global__ void __launch_bounds__(192) prep_a(const float* __restrict__ msg, const float* __restrict__ mem,
                                              const void* __restrict__ nid, const float* __restrict__ ts,
                                              float* __restrict__ out_lu) {
    int i = blockIdx.x, c = threadIdx.x;
    long long n = fetch_nid(nid, i);
    if (c == 0) out_lu[n] = ts[i];
    const float* s = (c < 128) ? (msg + (size_t)i * MSG + c * 8) : (mem + (size_t)n * MD + (c - 128) * 8);
    float4 a = ((const float4*)s)[0], b = ((const float4*)s)[1];
    uint4 u; __half* hp = (__half*)&u;
    hp[0] = __float2half_rn(a.x); hp[1] = __float2half_rn(a.y);
    hp[2] = __float2half_rn(a.z); hp[3] = __float2half_rn(a.w);
    hp[4] = __float2half_rn(b.x); hp[5] = __float2half_rn(b.y);
    hp[6] = __float2half_rn(b.z); hp[7] = __float2half_rn(b.w);
    size_t t = ((size_t)(i >> 7) * NKC + (c >> 3)) * TILEB;
    uint32_t bo = (uint32_t)((i & 127) * 128 + (c & 7) * 16);
    *(uint4*)((char*)g_A + t + sw128(bo)) = u;
}

// -------- fused GEMM (mma.sync) + GRU + scatter + overlapped skip-copy --------
// grid 4096 = 512 m-tiles x 8 n64-chunks. 512 threads = 16 warps:
//   warps 0-11: compute (gate g = w>>2, mb = w&3), barrier = bar.sync 1,384
//   warps 12-15: copy 64 non-updated memory rows (this CTA's slice), no barriers
__global__ void __launch_bounds__(512) gru_gemm(const float* __restrict__ mem, const void* __restrict__ nid,
                                                const float* __restrict__ bih, const float* __restrict__ bhh,
                                                float* __restrict__ out) {
    extern __shared__ char smem[];
    const uint32_t sb = s2u(smem);
    const int tid = threadIdx.x, w = tid >> 5, lane = tid & 31;
    const int mt = blockIdx.x >> 3, nc = blockIdx.x & 7;
    const uint32_t mbar = sb + MBAR_OFF;

    if (w >= 12) {
        // ---- copy warps: stream this CTA's 64 memory rows (8192 float4s) ----
        const float4* mv = (const float4*)mem;
        float4* ov = (float4*)out;
        const size_t base = (size_t)blockIdx.x * 8192 + (size_t)(w - 12) * 2048;
        #pragma unroll 4
        for (int j = 0; j < 64; j++) {
            size_t i = base + (size_t)j * 32 + lane;
            unsigned row = (unsigned)(i >> 7);
            if (!(g_bitmap[row >> 5] & (1u << (row & 31)))) ov[i] = mv[i];
        }
        return;
    }

    const int g = w >> 2, mb = w & 3;
    const int nc128 = nc >> 1, nh = nc & 1;

    if (tid == 0) {
        MBAR_INIT(mbar, 1); MBAR_INIT(mbar + 8, 1); MBAR_INIT(mbar + 16, 1);
        FENCE_ASYNC();
    }
    BAR_COMPUTE();

    const char* Ab = (const char*)g_A + (size_t)mt * NKC * TILEB;

    if (tid == 0) {
        #pragma unroll
        for (int c = 0; c < NSTG; c++) {
            uint32_t st = sb + c * STAGEB, mbr = mbar + c * 8;
            MBAR_EXPECT(mbr, STAGEB);
            bulk_g2s(st, Ab + (size_t)c * TILEB, TILEB, mbr);
            #pragma unroll
            for (int gg = 0; gg < 3; gg++)
                bulk_g2s(st + TILEB + gg * 8192,
                         (const char*)g_B + ((size_t)((gg * 4 + nc128) * NKC + c)) * TILEB + nh * 8192,
                         8192, mbr);
        }
    }

    float acc[2][8][4];
    #pragma unroll
    for (int t = 0; t < 2; t++)
        #pragma unroll
        for (int nt = 0; nt < 8; nt++)
            #pragma unroll
            for (int q = 0; q < 4; q++) acc[t][nt][q] = 0.0f;

    float* bufIn = (float*)(smem + BUF_IN_OFF);

    for (int c = 0; c < NKC; c++) {
        const int s = c % 3;
        MBAR_WAIT(mbar + s * 8, (c / 3) & 1);

        if (c == 16 && g == 2) {
            #pragma unroll
            for (int t = 0; t < 2; t++)
                #pragma unroll
                for (int nt = 0; nt < 8; nt++) {
                    int row0 = mb * 32 + t * 16 + (lane >> 2);
                    int col0 = nt * 8 + 2 * (lane & 3);
                    bufIn[col0 * EPIPITCH + row0]           = acc[t][nt][0];
                    bufIn[(col0 + 1) * EPIPITCH + row0]     = acc[t][nt][1];
                    bufIn[col0 * EPIPITCH + row0 + 8]       = acc[t][nt][2];
                    bufIn[(col0 + 1) * EPIPITCH + row0 + 8] = acc[t][nt][3];
                    acc[t][nt][0] = acc[t][nt][1] = acc[t][nt][2] = acc[t][nt][3] = 0.0f;
                }
        }

        const uint32_t stA = sb + s * STAGEB;
        const uint32_t stB = stA + TILEB + g * 8192;
        #pragma unroll
        for (int ks = 0; ks < 4; ks++) {
            uint32_t a[2][4];
            #pragma unroll
            for (int t = 0; t < 2; t++) {
                int row = mb * 32 + t * 16 + (lane & 7) + ((lane >> 3) & 1) * 8;
                int kb = ks * 32 + ((lane >> 4) & 1) * 16;
                ldsm4(a[t][0], a[t][1], a[t][2], a[t][3], stA + sw128(row * 128 + kb));
            }
            #pragma unroll
            for (int p = 0; p < 4; p++) {
                int rown = p * 16 + (lane & 7) + ((lane >> 4) & 1) * 8;
                int kb = ks * 32 + ((lane >> 3) & 1) * 16;
                uint32_t b0, b1, b2, b3;
                ldsm4(b0, b1, b2, b3, stB + sw128(rown * 128 + kb));
                #pragma unroll
                for (int t = 0; t < 2; t++) {
                    mma16816(acc[t][2 * p],     a[t][0], a[t][1], a[t][2], a[t][3], b0, b1);
                    mma16816(acc[t][2 * p + 1], a[t][0], a[t][1], a[t][2], a[t][3], b2, b3);
                }
            }
        }
        BAR_COMPUTE();
        if (tid == 0 && c + 3 < NKC) {
            const int cn = c + 3;
            uint32_t st = sb + s * STAGEB, mbr = mbar + s * 8;
            MBAR_EXPECT(mbr, STAGEB);
            bulk_g2s(st, Ab + (size_t)cn * TILEB, TILEB, mbr);
            #pragma unroll
            for (int gg = 0; gg < 3; gg++)
                bulk_g2s(st + TILEB + gg * 8192,
                         (const char*)g_B + ((size_t)((gg * 4 + nc128) * NKC + cn)) * TILEB + nh * 8192,
                         8192, mbr);
        }
    }

    float* bufG = (float*)(smem + (g == 0 ? BUF_R_OFF : (g == 1 ? BUF_Z_OFF : BUF_H_OFF)));
    #pragma unroll
    for (int t = 0; t < 2; t++)
        #pragma unroll
        for (int nt = 0; nt < 8; nt++) {
            int row0 = mb * 32 + t * 16 + (lane >> 2);
            int col0 = nt * 8 + 2 * (lane & 3);
            bufG[col0 * EPIPITCH + row0]           = acc[t][nt][0];
            bufG[(col0 + 1) * EPIPITCH + row0]     = acc[t][nt][1];
            bufG[col0 * EPIPITCH + row0 + 8]       = acc[t][nt][2];
            bufG[(col0 + 1) * EPIPITCH + row0 + 8] = acc[t][nt][3];
        }
    BAR_COMPUTE();

    if (w < 4) {
        const float* BR = (const float*)(smem + BUF_R_OFF);
        const float* BZ = (const float*)(smem + BUF_Z_OFF);
        const float* BH = (const float*)(smem + BUF_H_OFF);
        const float* BI = (const float*)(smem + BUF_IN_OFF);
        int row = w * 32 + lane;
        int gi = mt * 128 + row;
        long long n = fetch_nid(nid, gi);
        const float4* hp = (const float4*)(mem + (size_t)n * MD + nc * 64);
        float4* op = (float4*)(out + (size_t)n * MD + nc * 64);
        const int j0 = nc * 64;
        #pragma unroll 4
        for (int jq = 0; jq < 16; jq++) {
            float4 h4 = hp[jq];
            float o[4];
            const float* hv = (const float*)&h4;
            #pragma unroll
            for (int q = 0; q < 4; q++) {
                int j = jq * 4 + q;
                int jg = j0 + j;
                float cr = BR[j * EPIPITCH + row] + bih[jg] + bhh[jg];
                float cz = BZ[j * EPIPITCH + row] + bih[512 + jg] + bhh[512 + jg];
                float ci = BI[j * EPIPITCH + row] + bih[1024 + jg];
                float ch = BH[j * EPIPITCH + row] + bhh[1024 + jg];
                float r = 1.0f / (1.0f + __expf(-cr));
                float z = 1.0f / (1.0f + __expf(-cz));
                float e = __expf(2.0f * (ci + r * ch));
                float nn = 1.0f - 2.0f / (e + 1.0f);
                o[q] = (1.0f - z) * nn + z * hv[q];
            }
            op[jq] = make_float4(o[0], o[1], o[2], o[3]);
        }
    }
}

extern "C" void kernel_launch(void* const* d_in, const int* in_sizes, int n_in,
                              void* d_out, int out_size) {
    const float* mem = (const float*)d_in[0];
    const float* lu = (const float*)d_in[1];
    const void* nid = d_in[2];
    const float* msg = (const float*)d_in[3];
    const float* ts = (const float*)d_in[4];
    const float* Wih = (const float*)d_in[5];
    const float* Whh = (const float*)d_in[6];
    const float* bih = (const float*)d_in[7];
    const float* bhh = (const float*)d_in[8];
    float* out = (float*)d_out;
    float* out_lu = out + (size_t)NN * MD;

    cudaFuncSetAttribute(gru_gemm, cudaFuncAttributeMaxDynamicSharedMemorySize, SMEMSZ);

    detect_nid<<<1, 128>>>((const int*)nid);
    bm_clear<<<(NN / 32 + 255) / 256, 256>>>();
    bm_set<<<(NU + 255) / 256, 256>>>(nid);
    copy_lu<<<(NN / 4 + 255) / 256, 256>>>((const float4*)lu, (float4*)out_lu);
    prep_b<<<1536, 192>>>(Wih, Whh);
    prep_a<<<NU, 192>>>(msg, mem, nid, ts, out_lu);
    gru_gemm<<<4096, 512, SMEMSZ>>>(mem, nid, bih, bhh, out);
}